// round 14
// baseline (speedup 1.0000x reference)
#include <cuda_runtime.h>
#include <cuda_fp16.h>
#include <math.h>
#include <stdint.h>

// Problem constants
#define B_  4
#define S_  1024
#define BH  64     // B*H

// ---------------------------------------------------------------------------
// Scratch. "h" arrays hold packed fp16 pairs: word w = h(x[2w]) | h(x[2w+1])<<16
// ---------------------------------------------------------------------------
static __device__ uint32_t g_INh[(size_t)5 * 2097152];   // [qa,qg,ka,kg,va] inputs
static __device__ uint32_t g_Wh[(size_t)4194304];        // Wqa..Wva,Wgate,Winfo
static __device__ uint32_t g_Qh[(size_t)BH * S_ * 64];   // [bh,s,64w] (qa|qg), pre-scaled
static __device__ uint32_t g_Kh[(size_t)BH * S_ * 64];
static __device__ uint32_t g_Vh[(size_t)BH * 64 * 512];  // transposed [bh,j,s] fp16
static __device__ uint32_t g_MB[(size_t)B_ * S_ * 512];  // mask bias packed fp16 (0 / -30000)
static __device__ uint32_t g_Xh[(size_t)4096 * 512];     // attn out packed
static __device__ float    g_G [(size_t)4096 * 1024];    // gate fp32

#define OW_QA 0u
#define OW_QG 524288u
#define OW_KA 1048576u
#define OW_KG 1572864u
#define OW_VA 2097152u
#define OW_GATE 2621440u
#define OW_INFO 3670016u

// ---------------------------------------------------------------------------
__device__ __forceinline__ uint32_t pack_h2(float x, float y) {
    __half2 h = __floats2half2_rn(x, y);
    return *(uint32_t*)&h;
}

__device__ __forceinline__ void mma_fp16(float* c,
    uint32_t a0, uint32_t a1, uint32_t a2, uint32_t a3,
    uint32_t b0, uint32_t b1)
{
    asm volatile(
        "mma.sync.aligned.m16n8k16.row.col.f32.f16.f16.f32 "
        "{%0,%1,%2,%3},{%4,%5,%6,%7},{%8,%9},{%0,%1,%2,%3};"
        : "+f"(c[0]), "+f"(c[1]), "+f"(c[2]), "+f"(c[3])
        : "r"(a0), "r"(a1), "r"(a2), "r"(a3), "r"(b0), "r"(b1));
}

__device__ __forceinline__ uint32_t smem_u32(const void* p) {
    uint32_t a;
    asm("{ .reg .u64 t; cvta.to.shared.u64 t, %1; cvt.u32.u64 %0, t; }" : "=r"(a) : "l"(p));
    return a;
}

__device__ __forceinline__ void cp16(uint32_t dst, const void* src) {
    asm volatile("cp.async.ca.shared.global [%0], [%1], 16;" :: "r"(dst), "l"(src));
}
#define CP_COMMIT() asm volatile("cp.async.commit_group;" ::: "memory")
#define CP_WAIT1()  asm volatile("cp.async.wait_group 1;" ::: "memory")
#define CP_WAIT0()  asm volatile("cp.async.wait_group 0;" ::: "memory")

// ---------------------------------------------------------------------------
// Conversion kernels (once per launch)
// ---------------------------------------------------------------------------
__global__ __launch_bounds__(256) void conv_in_kernel(
    const float* __restrict__ q_g, const float* __restrict__ k_g,
    const float* __restrict__ q_a, const float* __restrict__ k_a,
    const float* __restrict__ v_a)
{
    const int z = blockIdx.y;
    const float* src = (z == 0) ? q_a : (z == 1) ? q_g : (z == 2) ? k_a
                     : (z == 3) ? k_g : v_a;
    const size_t i = (size_t)blockIdx.x * 256 + threadIdx.x;
    float4 v = ((const float4*)src)[i];
    const size_t w = (size_t)z * 2097152 + i * 2;
    g_INh[w]     = pack_h2(v.x, v.y);
    g_INh[w + 1] = pack_h2(v.z, v.w);
}

__global__ __launch_bounds__(256) void conv_w_kernel(
    const float* __restrict__ Wqa, const float* __restrict__ Wqg,
    const float* __restrict__ Wka, const float* __restrict__ Wkg,
    const float* __restrict__ Wva, const float* __restrict__ Wgate,
    const float* __restrict__ Winfo)
{
    const int z = blockIdx.y;
    const float* src; size_t offw; size_t nf4;
    switch (z) {
        case 0: src = Wqa;   offw = OW_QA;   nf4 = 262144; break;
        case 1: src = Wqg;   offw = OW_QG;   nf4 = 262144; break;
        case 2: src = Wka;   offw = OW_KA;   nf4 = 262144; break;
        case 3: src = Wkg;   offw = OW_KG;   nf4 = 262144; break;
        case 4: src = Wva;   offw = OW_VA;   nf4 = 262144; break;
        case 5: src = Wgate; offw = OW_GATE; nf4 = 524288; break;
        default: src = Winfo; offw = OW_INFO; nf4 = 262144; break;
    }
    for (size_t i = (size_t)blockIdx.x * 256 + threadIdx.x; i < nf4; i += 262144) {
        float4 v = ((const float4*)src)[i];
        const size_t w = offw + i * 2;
        g_Wh[w]     = pack_h2(v.x, v.y);
        g_Wh[w + 1] = pack_h2(v.z, v.w);
    }
}

__global__ __launch_bounds__(256) void conv_mask_kernel(const int* __restrict__ mask)
{
    const size_t i = (size_t)blockIdx.x * 256 + threadIdx.x;
    const int2 mk = ((const int2*)mask)[i];
    g_MB[i] = pack_h2(mk.x == 0 ? -30000.0f : 0.0f,
                      mk.y == 0 ? -30000.0f : 0.0f);
}

// ---------------------------------------------------------------------------
// fp16 GEMM via cp.async 3-stage pipeline.
// ---------------------------------------------------------------------------
#define GSMEM 61440
typedef uint32_t (*SmT)[20];

__device__ __forceinline__ void issue_stage(
    uint32_t smu, int stage,
    const uint32_t* __restrict__ Ahp, int ldaw,
    const uint32_t* __restrict__ A2h, int kspw,
    const uint32_t* __restrict__ Bhp, int ldbw,
    int m0, int n0, int kw0)
{
    const int tid = threadIdx.x;
    const uint32_t sbase = smu + (uint32_t)stage * 20480u;
    #pragma unroll
    for (int c = 0; c < 2; c++) {
        const int cid = tid + c * 256;
        const int row = cid >> 2, cw = (cid & 3) << 2;
        const int gw = kw0 + cw;
        const uint32_t* srcA;
        if (gw >= kspw) srcA = A2h + (size_t)(m0 + row) * 512 + (gw - kspw);
        else            srcA = Ahp + (size_t)(m0 + row) * ldaw + gw;
        const uint32_t dstA = sbase + (uint32_t)((row * 20 + cw) * 4);
        cp16(dstA, srcA);
        cp16(dstA + 10240u, Bhp + (size_t)(n0 + row) * ldbw + gw);
    }
}

__device__ __forceinline__ void mma_stage(
    uint32_t* stg, int wm, int wn, int g, int t, float acc[2][8][4])
{
    SmT Ah = (SmT)stg;
    SmT Bh = (SmT)(stg + 2560);
    #pragma unroll
    for (int kk = 0; kk < 2; kk++) {
        const int pc = kk * 8;
        uint32_t ah[2][4];
        #pragma unroll
        for (int mt = 0; mt < 2; mt++) {
            #pragma unroll
            for (int q = 0; q < 4; q++) {
                const int row = wm + mt * 16 + g + (q & 1) * 8;
                const int col = pc + t + (q >> 1) * 4;
                ah[mt][q] = Ah[row][col];
            }
        }
        #pragma unroll
        for (int nf = 0; nf < 8; nf++) {
            const int rb = wn + nf * 8 + g;
            const uint32_t b0 = Bh[rb][pc + t], b1 = Bh[rb][pc + t + 4];
            #pragma unroll
            for (int mt = 0; mt < 2; mt++)
                mma_fp16(acc[mt][nf], ah[mt][0], ah[mt][1], ah[mt][2], ah[mt][3], b0, b1);
        }
    }
}

__device__ __forceinline__ void gemm_fp16_ca(
    uint32_t* sm,
    const uint32_t* __restrict__ Ahp, int ldaw,
    const uint32_t* __restrict__ A2h, int kspw,
    const uint32_t* __restrict__ Bhp, int ldbw,
    int Kw, int m0, int n0, float acc[2][8][4])
{
    const uint32_t smu = smem_u32(sm);
    const int warp = threadIdx.x >> 5, lane = threadIdx.x & 31;
    const int wm = (warp & 3) * 32, wn = (warp >> 2) * 64;
    const int g = lane >> 2, t = lane & 3;
    const int nK = Kw >> 4;

    issue_stage(smu, 0, Ahp, ldaw, A2h, kspw, Bhp, ldbw, m0, n0, 0);
    CP_COMMIT();
    issue_stage(smu, 1, Ahp, ldaw, A2h, kspw, Bhp, ldbw, m0, n0, 16);
    CP_COMMIT();

    for (int kt = 0; kt < nK; kt++) {
        CP_WAIT1();
        __syncthreads();
        if (kt + 2 < nK) {
            issue_stage(smu, (kt + 2) % 3, Ahp, ldaw, A2h, kspw, Bhp, ldbw,
                        m0, n0, (kt + 2) * 16);
            CP_COMMIT();
        }
        mma_stage(sm + (kt % 3) * 5120, wm, wn, g, t, acc);
    }
}

// ---------------------------------------------------------------------------
// Kernel 1: gate (z=0, longest first) + 5 projections (z=1..5).
// Q written pre-scaled by 1/sqrt(128).
// ---------------------------------------------------------------------------
__global__ __launch_bounds__(256, 2) void projgate_kernel(
    const float* __restrict__ bqa, const float* __restrict__ bqg,
    const float* __restrict__ bka, const float* __restrict__ bkg,
    const float* __restrict__ bva, const float* __restrict__ bgate)
{
    extern __shared__ uint32_t sm[];
    const int m0 = blockIdx.y * 128;
    const int n0 = blockIdx.x * 128;
    const int lane = threadIdx.x & 31, warp = threadIdx.x >> 5;
    const int wm = (warp & 3) * 32, wn = (warp >> 2) * 64;
    const int g = lane >> 2, t = lane & 3;
    float acc[2][8][4] = {};

    if (blockIdx.z == 0) {
        gemm_fp16_ca(sm, g_INh, 512, g_INh + 2097152, 512,
                     g_Wh + OW_GATE, 1024, 1024, m0, n0, acc);

        #pragma unroll
        for (int nf = 0; nf < 8; nf++) {
            const int n = n0 + wn + nf * 8 + 2 * t;
            const float bx = bgate[n], by = bgate[n + 1];
            #pragma unroll
            for (int mt = 0; mt < 2; mt++) {
                #pragma unroll
                for (int h2 = 0; h2 < 2; h2++) {
                    const int m = m0 + wm + mt * 16 + g + h2 * 8;
                    float2 v;
                    v.x = 1.0f / (1.0f + __expf(-(acc[mt][nf][h2 * 2 + 0] + bx)));
                    v.y = 1.0f / (1.0f + __expf(-(acc[mt][nf][h2 * 2 + 1] + by)));
                    *(float2*)&g_G[(size_t)m * 1024 + n] = v;
                }
            }
        }
    } else {
        const int p = blockIdx.z - 1;
        const uint32_t* Ahp = g_INh + (size_t)p * 2097152;
        const uint32_t woff = (p == 0) ? OW_QA : (p == 1) ? OW_QG : (p == 2) ? OW_KA
                            : (p == 3) ? OW_KG : OW_VA;
        const float* bias = (p == 0) ? bqa : (p == 1) ? bqg : (p == 2) ? bka
                          : (p == 3) ? bkg : bva;
        gemm_fp16_ca(sm, Ahp, 512, nullptr, 1 << 30, g_Wh + woff, 512, 512, m0, n0, acc);

        const float qs = (p < 2) ? 0.08838834764831845f : 1.0f;
        #pragma unroll
        for (int nf = 0; nf < 8; nf++) {
            const int n  = n0 + wn + nf * 8 + 2 * t;
            const int h  = n >> 6, jj = n & 63;
            const float bx = bias[n], by = bias[n + 1];
            #pragma unroll
            for (int mt = 0; mt < 2; mt++) {
                #pragma unroll
                for (int h2 = 0; h2 < 2; h2++) {
                    const int m = m0 + wm + mt * 16 + g + h2 * 8;
                    const int b = m >> 10, s = m & 1023;
                    const size_t bhh = (size_t)(b * 16 + h);
                    const float vx = (acc[mt][nf][h2 * 2 + 0] + bx) * qs;
                    const float vy = (acc[mt][nf][h2 * 2 + 1] + by) * qs;
                    if (p == 4) {
                        __half* Vp = (__half*)g_Vh;
                        Vp[(bhh * 64 + jj)     * 1024 + s] = __float2half_rn(vx);
                        Vp[(bhh * 64 + jj + 1) * 1024 + s] = __float2half_rn(vy);
                    } else {
                        const size_t widx = (bhh * 1024 + s) * 64 + ((p & 1) ? 32 : 0) + (jj >> 1);
                        if (p < 2) g_Qh[widx] = pack_h2(vx, vy);
                        else       g_Kh[widx] = pack_h2(vx, vy);
                    }
                }
            }
        }
    }
}

// ---------------------------------------------------------------------------
// Kernel 3: fused flash attention WITHOUT online-max (scores bounded; masked
// entries get -30000 bias -> exp underflows to 0). One barrier per tile.
// smem: Qh [128][68] @0, Kst0 @34816, Kst1 @69632, Vst0 @104448, Vst1 @121856,
// redsum @139264 [2][128]. Osum reuses Kst0.
// ---------------------------------------------------------------------------
#define ATTN_SMEM 140288

__global__ __launch_bounds__(256) void attn_kernel()
{
    extern __shared__ char smem[];
    uint32_t (*Qh)[68] = (uint32_t(*)[68])(smem);
    float* redsum = (float*)(smem + 139264);
    float* Osum   = (float*)(smem + 34816);
    const uint32_t smu = smem_u32(smem);

    const int tid  = threadIdx.x;
    const int warp = tid >> 5, lane = tid & 31;
    const int wm = (warp & 3) * 32;
    const int wn = (warp >> 2);
    const int g  = lane >> 2;
    const int t  = lane & 3;

    const int bh = blockIdx.y;
    const int b  = bh >> 4, h = bh & 15;
    const int m0 = blockIdx.x * 128;

    const uint32_t* Qhg = g_Qh + ((size_t)bh << 16);
    const uint32_t* Khg = g_Kh + ((size_t)bh << 16);
    const uint32_t* Vhg = g_Vh + (size_t)bh * 32768;

    const int lr16 = tid >> 4;
    const int cw4  = (tid & 15) * 4;

    // Q tile (once)
    {
        const int lrow = tid >> 5;
        const int pcw  = (tid & 31) * 2;
        #pragma unroll
        for (int i = 0; i < 16; i++) {
            const int r = lrow + i * 8;
            *(uint2*)&Qh[r][pcw] = *(const uint2*)(Qhg + (size_t)(m0 + r) * 64 + pcw);
        }
    }

    auto issue_kv = [&](int nt, int st) {
        const int n0 = nt * 128;
        const uint32_t kbase = smu + 34816u + (uint32_t)st * 34816u;
        const uint32_t vbase = smu + 104448u + (uint32_t)st * 17408u;
        #pragma unroll
        for (int i = 0; i < 8; i++) {
            const int r = lr16 + i * 16;
            cp16(kbase + (uint32_t)((r * 68 + cw4) * 4),
                 Khg + (size_t)(n0 + r) * 64 + cw4);
        }
        #pragma unroll
        for (int i = 0; i < 4; i++) {
            const int r = lr16 + i * 16;
            cp16(vbase + (uint32_t)((r * 68 + cw4) * 4),
                 Vhg + (size_t)r * 512 + (n0 >> 1) + cw4);
        }
        CP_COMMIT();
    };

    float o[2][8][4] = {};
    float lrun[2][2] = {};

    issue_kv(0, 0);

    for (int nt = 0; nt < 8; nt++) {
        CP_WAIT0();
        __syncthreads();
        if (nt + 1 < 8)
            issue_kv(nt + 1, (nt + 1) & 1);

        const int st = nt & 1;
        uint32_t (*Kh)[68] = (uint32_t(*)[68])(smem + 34816 + st * 34816);
        uint32_t (*Vh)[68] = (uint32_t(*)[68])(smem + 104448 + st * 17408);
        const int n0 = nt * 128;

        // ---- S = Q K^T (Q pre-scaled by 1/sqrt(128)) ----
        float s[2][8][4] = {};
        #pragma unroll
        for (int ks = 0; ks < 8; ks++) {
            const int pc = ks * 8;
            uint32_t ah[2][4];
            #pragma unroll
            for (int mt = 0; mt < 2; mt++) {
                #pragma unroll
                for (int q = 0; q < 4; q++) {
                    const int row = wm + mt * 16 + g + (q & 1) * 8;
                    const int col = pc + t + (q >> 1) * 4;
                    ah[mt][q] = Qh[row][col];
                }
            }
            #pragma unroll
            for (int nf = 0; nf < 8; nf++) {
                const int rb = wn * 64 + nf * 8 + g;
                const uint32_t b0 = Kh[rb][pc + t], b1 = Kh[rb][pc + t + 4];
                #pragma unroll
                for (int mt = 0; mt < 2; mt++)
                    mma_fp16(s[mt][nf], ah[mt][0], ah[mt][1], ah[mt][2], ah[mt][3], b0, b1);
            }
        }

        // ---- p = exp(s + bias); accumulate row sums (no max needed) ----
        #pragma unroll
        for (int mt = 0; mt < 2; mt++) {
            #pragma unroll
            for (int h2 = 0; h2 < 2; h2++) {
                const int rglob = m0 + wm + mt * 16 + g + h2 * 8;
                float ps = 0.0f;
                #pragma unroll
                for (int nf = 0; nf < 8; nf++) {
                    const int ncol = n0 + wn * 64 + nf * 8 + 2 * t;
                    const uint32_t mb = g_MB[((size_t)b << 19) + ((size_t)rglob << 9) + (ncol >> 1)];
                    const float2 bias = __half22float2(*(const __half2*)&mb);
                    const float p0 = __expf(s[mt][nf][h2 * 2 + 0] + bias.x);
                    const float p1 = __expf(s[mt][nf][h2 * 2 + 1] + bias.y);
                    s[mt][nf][h2 * 2 + 0] = p0;
                    s[mt][nf][h2 * 2 + 1] = p1;
                    ps += p0 + p1;
                }
                lrun[mt][h2] += ps;
            }
        }

        // ---- O += P V ----
        #pragma unroll
        for (int ks2 = 0; ks2 < 4; ks2++) {
            uint32_t ah[2][4];
            #pragma unroll
            for (int mt = 0; mt < 2; mt++) {
                ah[mt][0] = pack_h2(s[mt][2 * ks2][0],     s[mt][2 * ks2][1]);
                ah[mt][1] = pack_h2(s[mt][2 * ks2][2],     s[mt][2 * ks2][3]);
                ah[mt][2] = pack_h2(s[mt][2 * ks2 + 1][0], s[mt][2 * ks2 + 1][1]);
                ah[mt][3] = pack_h2(s[mt][2 * ks2 + 1][2], s[mt][2 * ks2 + 1][3]);
            }
            const int vcol = wn * 32 + ks2 * 8 + t;
            #pragma unroll
            for (int nf = 0; nf < 8; nf++) {
                const int rv = nf * 8 + g;
                const uint32_t b0 = Vh[rv][vcol], b1 = Vh[rv][vcol + 4];
                #pragma unroll
                for (int mt = 0; mt < 2; mt++)
                    mma_fp16(o[mt][nf], ah[mt][0], ah[mt][1], ah[mt][2], ah[mt][3], b0, b1);
            }
        }
    }

    // ---- final row-sum reduction (once) ----
    #pragma unroll
    for (int mt = 0; mt < 2; mt++)
        #pragma unroll
        for (int h2 = 0; h2 < 2; h2++) {
            lrun[mt][h2] += __shfl_xor_sync(0xffffffffu, lrun[mt][h2], 1);
            lrun[mt][h2] += __shfl_xor_sync(0xffffffffu, lrun[mt][h2], 2);
        }

    // ---- epilogue: combine the two n-warps' partials, normalize, store ----
    __syncthreads();
    if (wn == 1) {
        #pragma unroll
        for (int mt = 0; mt < 2; mt++)
            #pragma unroll
            for (int h2 = 0; h2 < 2; h2++) {
                const int rl = wm + mt * 16 + g + h2 * 8;
                if (t == 0) redsum[rl] = lrun[mt][h2];
                #pragma unroll
                for (int nf = 0; nf < 8; nf++) {
                    float2 v;
                    v.x = o[mt][nf][h2 * 2 + 0];
                    v.y = o[mt][nf][h2 * 2 + 1];
                    *(float2*)&Osum[rl * 66 + nf * 8 + 2 * t] = v;
                }
            }
    }
    __syncthreads();
    if (wn == 0) {
        #pragma unroll
        for (int mt = 0; mt < 2; mt++)
            #pragma unroll
            for (int h2 = 0; h2 < 2; h2++) {
                const int rl = wm + mt * 16 + g + h2 * 8;
                const float inv = 1.0f / (lrun[mt][h2] + redsum[rl]);
                #pragma unroll
                for (int nf = 0; nf < 8; nf++) {
                    const int c = nf * 8 + 2 * t;
                    float2 p = *(float2*)&Osum[rl * 66 + c];
                    const float vx = (o[mt][nf][h2 * 2 + 0] + p.x) * inv;
                    const float vy = (o[mt][nf][h2 * 2 + 1] + p.y) * inv;
                    g_Xh[(size_t)(b * 1024 + m0 + rl) * 512 + ((h * 64 + c) >> 1)] = pack_h2(vx, vy);
                }
            }
    }
}

// ---------------------------------------------------------------------------
// Kernel 4: out = gate * (X @ Winfo^T + binfo)
// ---------------------------------------------------------------------------
__global__ __launch_bounds__(256, 2) void info_kernel(
    const float* __restrict__ binfo, float* __restrict__ out)
{
    extern __shared__ uint32_t sm[];
    const int m0 = blockIdx.y * 128;
    const int n0 = blockIdx.x * 128;
    float acc[2][8][4] = {};
    gemm_fp16_ca(sm, g_Xh, 512, nullptr, 1 << 30, g_Wh + OW_INFO, 512, 512, m0, n0, acc);

    const int lane = threadIdx.x & 31, warp = threadIdx.x >> 5;
    const int wm = (warp & 3) * 32, wn = (warp >> 2) * 64;
    const int g = lane >> 2, t = lane & 3;

    #pragma unroll
    for (int nf = 0; nf < 8; nf++) {
        const int n = n0 + wn + nf * 8 + 2 * t;
        const float bx = binfo[n], by = binfo[n + 1];
        #pragma unroll
        for (int mt = 0; mt < 2; mt++) {
            #pragma unroll
            for (int h2 = 0; h2 < 2; h2++) {
                const int m = m0 + wm + mt * 16 + g + h2 * 8;
                const float2 gg = *(const float2*)&g_G[(size_t)m * 1024 + n];
                float2 v;
                v.x = gg.x * (acc[mt][nf][h2 * 2 + 0] + bx);
                v.y = gg.y * (acc[mt][nf][h2 * 2 + 1] + by);
                *(float2*)&out[(size_t)m * 1024 + n] = v;
            }
        }
    }
}

// ---------------------------------------------------------------------------
extern "C" void kernel_launch(void* const* d_in, const int* in_sizes, int n_in,
                              void* d_out, int out_size)
{
    (void)in_sizes; (void)n_in; (void)out_size;
    const float* query_g = (const float*)d_in[0];
    const float* key_g   = (const float*)d_in[1];
    const float* query_a = (const float*)d_in[2];
    const float* key_a   = (const float*)d_in[3];
    const float* value_a = (const float*)d_in[4];
    const int*   mask    = (const int*)  d_in[5];
    const float* Wqg = (const float*)d_in[6];  const float* bqg = (const float*)d_in[7];
    const float* Wkg = (const float*)d_in[8];  const float* bkg = (const float*)d_in[9];
    const float* Wqa = (const float*)d_in[10]; const float* bqa = (const float*)d_in[11];
    const float* Wka = (const float*)d_in[12]; const float* bka = (const float*)d_in[13];
    const float* Wva = (const float*)d_in[14]; const float* bva = (const float*)d_in[15];
    const float* Wgate = (const float*)d_in[16]; const float* bgate = (const float*)d_in[17];
    const float* Winfo = (const float*)d_in[18]; const float* binfo = (const float*)d_in[19];

    static int attr_set = 0;
    if (!attr_set) {
        cudaFuncSetAttribute(attn_kernel, cudaFuncAttributeMaxDynamicSharedMemorySize, ATTN_SMEM);
        cudaFuncSetAttribute(projgate_kernel, cudaFuncAttributeMaxDynamicSharedMemorySize, GSMEM);
        cudaFuncSetAttribute(info_kernel, cudaFuncAttributeMaxDynamicSharedMemorySize, GSMEM);
        attr_set = 1;
    }

    dim3 blk(256);
    conv_in_kernel<<<dim3(4096, 5), blk>>>(query_g, key_g, query_a, key_a, value_a);
    conv_w_kernel<<<dim3(1024, 7), blk>>>(Wqa, Wqg, Wka, Wkg, Wva, Wgate, Winfo);
    conv_mask_kernel<<<8192, blk>>>(mask);
    projgate_kernel<<<dim3(8, 32, 6), blk, GSMEM>>>(bqa, bqg, bka, bkg, bva, bgate);
    attn_kernel<<<dim3(8, 64), blk, ATTN_SMEM>>>();
    info_kernel<<<dim3(8, 32, 1), blk, GSMEM>>>(binfo, (float*)d_out);
}

// round 15
// speedup vs baseline: 1.0278x; 1.0278x over previous
#include <cuda_runtime.h>
#include <cuda_fp16.h>
#include <math.h>
#include <stdint.h>

// Problem constants
#define B_  4
#define S_  1024
#define BH  64     // B*H

// ---------------------------------------------------------------------------
// Scratch. "h" arrays hold packed fp16 pairs: word w = h(x[2w]) | h(x[2w+1])<<16
// ---------------------------------------------------------------------------
static __device__ uint32_t g_INh[(size_t)5 * 2097152];   // [qa,qg,ka,kg,va] inputs
static __device__ uint32_t g_Wh[(size_t)4194304];        // Wqa..Wva,Wgate,Winfo
static __device__ uint32_t g_Qh[(size_t)BH * S_ * 64];   // [bh,s,64w] (qa|qg), pre-scaled
static __device__ uint32_t g_Kh[(size_t)BH * S_ * 64];
static __device__ uint32_t g_Vh[(size_t)BH * 64 * 512];  // transposed [bh,j,s] fp16
static __device__ uint32_t g_MB[(size_t)B_ * S_ * 512];  // mask bias packed fp16 (0 / -30000)
static __device__ uint32_t g_Xh[(size_t)4096 * 512];     // attn out packed
static __device__ float    g_G [(size_t)4096 * 1024];    // gate fp32

#define OW_QA 0u
#define OW_QG 524288u
#define OW_KA 1048576u
#define OW_KG 1572864u
#define OW_VA 2097152u
#define OW_GATE 2621440u
#define OW_INFO 3670016u

// ---------------------------------------------------------------------------
__device__ __forceinline__ uint32_t pack_h2(float x, float y) {
    __half2 h = __floats2half2_rn(x, y);
    return *(uint32_t*)&h;
}

__device__ __forceinline__ void mma_fp16(float* c,
    uint32_t a0, uint32_t a1, uint32_t a2, uint32_t a3,
    uint32_t b0, uint32_t b1)
{
    asm volatile(
        "mma.sync.aligned.m16n8k16.row.col.f32.f16.f16.f32 "
        "{%0,%1,%2,%3},{%4,%5,%6,%7},{%8,%9},{%0,%1,%2,%3};"
        : "+f"(c[0]), "+f"(c[1]), "+f"(c[2]), "+f"(c[3])
        : "r"(a0), "r"(a1), "r"(a2), "r"(a3), "r"(b0), "r"(b1));
}

__device__ __forceinline__ uint32_t smem_u32(const void* p) {
    uint32_t a;
    asm("{ .reg .u64 t; cvta.to.shared.u64 t, %1; cvt.u32.u64 %0, t; }" : "=r"(a) : "l"(p));
    return a;
}

__device__ __forceinline__ void cp16(uint32_t dst, const void* src) {
    asm volatile("cp.async.ca.shared.global [%0], [%1], 16;" :: "r"(dst), "l"(src));
}
#define CP_COMMIT() asm volatile("cp.async.commit_group;" ::: "memory")
#define CP_WAIT2()  asm volatile("cp.async.wait_group 2;" ::: "memory")
#define CP_WAIT0()  asm volatile("cp.async.wait_group 0;" ::: "memory")

// ---------------------------------------------------------------------------
// Merged conversion kernel. grid = (4096, 13).
// z 0..4: inputs (1048576 float4 each). z 5..11: weights. z 12: mask (x2).
// ---------------------------------------------------------------------------
__global__ __launch_bounds__(256) void conv_all_kernel(
    const float* __restrict__ q_g, const float* __restrict__ k_g,
    const float* __restrict__ q_a, const float* __restrict__ k_a,
    const float* __restrict__ v_a,
    const float* __restrict__ Wqa, const float* __restrict__ Wqg,
    const float* __restrict__ Wka, const float* __restrict__ Wkg,
    const float* __restrict__ Wva, const float* __restrict__ Wgate,
    const float* __restrict__ Winfo,
    const int* __restrict__ mask)
{
    const int z = blockIdx.y;
    const size_t i = (size_t)blockIdx.x * 256 + threadIdx.x;

    if (z < 5) {
        const float* src = (z == 0) ? q_a : (z == 1) ? q_g : (z == 2) ? k_a
                         : (z == 3) ? k_g : v_a;
        float4 v = ((const float4*)src)[i];
        const size_t w = (size_t)z * 2097152 + i * 2;
        g_INh[w]     = pack_h2(v.x, v.y);
        g_INh[w + 1] = pack_h2(v.z, v.w);
    } else if (z < 12) {
        const int wz = z - 5;
        const float* src; size_t offw; size_t nf4;
        switch (wz) {
            case 0: src = Wqa;   offw = OW_QA;   nf4 = 262144; break;
            case 1: src = Wqg;   offw = OW_QG;   nf4 = 262144; break;
            case 2: src = Wka;   offw = OW_KA;   nf4 = 262144; break;
            case 3: src = Wkg;   offw = OW_KG;   nf4 = 262144; break;
            case 4: src = Wva;   offw = OW_VA;   nf4 = 262144; break;
            case 5: src = Wgate; offw = OW_GATE; nf4 = 524288; break;
            default: src = Winfo; offw = OW_INFO; nf4 = 262144; break;
        }
        if (i < nf4) {
            float4 v = ((const float4*)src)[i];
            const size_t w = offw + i * 2;
            g_Wh[w]     = pack_h2(v.x, v.y);
            g_Wh[w + 1] = pack_h2(v.z, v.w);
        }
    } else {
        // mask: 2097152 int2 total, each thread handles 2
        #pragma unroll
        for (int r = 0; r < 2; r++) {
            const size_t j = i + (size_t)r * 1048576;
            const int2 mk = ((const int2*)mask)[j];
            g_MB[j] = pack_h2(mk.x == 0 ? -30000.0f : 0.0f,
                              mk.y == 0 ? -30000.0f : 0.0f);
        }
    }
}

// ---------------------------------------------------------------------------
// fp16 GEMM via cp.async 4-stage pipeline.
// Stage: A [128][20]w @ +0, B [128][20]w @ +2560w. Stage stride 5120 words.
// GSMEM = 4 * 20480 B = 81920.
// ---------------------------------------------------------------------------
#define GSMEM 81920
typedef uint32_t (*SmT)[20];

__device__ __forceinline__ void issue_stage(
    uint32_t smu, int stage,
    const uint32_t* __restrict__ Ahp, int ldaw,
    const uint32_t* __restrict__ A2h, int kspw,
    const uint32_t* __restrict__ Bhp, int ldbw,
    int m0, int n0, int kw0)
{
    const int tid = threadIdx.x;
    const uint32_t sbase = smu + (uint32_t)stage * 20480u;
    #pragma unroll
    for (int c = 0; c < 2; c++) {
        const int cid = tid + c * 256;
        const int row = cid >> 2, cw = (cid & 3) << 2;
        const int gw = kw0 + cw;
        const uint32_t* srcA;
        if (gw >= kspw) srcA = A2h + (size_t)(m0 + row) * 512 + (gw - kspw);
        else            srcA = Ahp + (size_t)(m0 + row) * ldaw + gw;
        const uint32_t dstA = sbase + (uint32_t)((row * 20 + cw) * 4);
        cp16(dstA, srcA);
        cp16(dstA + 10240u, Bhp + (size_t)(n0 + row) * ldbw + gw);
    }
}

__device__ __forceinline__ void mma_stage(
    uint32_t* stg, int wm, int wn, int g, int t, float acc[2][8][4])
{
    SmT Ah = (SmT)stg;
    SmT Bh = (SmT)(stg + 2560);
    #pragma unroll
    for (int kk = 0; kk < 2; kk++) {
        const int pc = kk * 8;
        uint32_t ah[2][4];
        #pragma unroll
        for (int mt = 0; mt < 2; mt++) {
            #pragma unroll
            for (int q = 0; q < 4; q++) {
                const int row = wm + mt * 16 + g + (q & 1) * 8;
                const int col = pc + t + (q >> 1) * 4;
                ah[mt][q] = Ah[row][col];
            }
        }
        #pragma unroll
        for (int nf = 0; nf < 8; nf++) {
            const int rb = wn + nf * 8 + g;
            const uint32_t b0 = Bh[rb][pc + t], b1 = Bh[rb][pc + t + 4];
            #pragma unroll
            for (int mt = 0; mt < 2; mt++)
                mma_fp16(acc[mt][nf], ah[mt][0], ah[mt][1], ah[mt][2], ah[mt][3], b0, b1);
        }
    }
}

__device__ __forceinline__ void gemm_fp16_ca(
    uint32_t* sm,
    const uint32_t* __restrict__ Ahp, int ldaw,
    const uint32_t* __restrict__ A2h, int kspw,
    const uint32_t* __restrict__ Bhp, int ldbw,
    int Kw, int m0, int n0, float acc[2][8][4])
{
    const uint32_t smu = smem_u32(sm);
    const int warp = threadIdx.x >> 5, lane = threadIdx.x & 31;
    const int wm = (warp & 3) * 32, wn = (warp >> 2) * 64;
    const int g = lane >> 2, t = lane & 3;
    const int nK = Kw >> 4;

    issue_stage(smu, 0, Ahp, ldaw, A2h, kspw, Bhp, ldbw, m0, n0, 0);
    CP_COMMIT();
    issue_stage(smu, 1, Ahp, ldaw, A2h, kspw, Bhp, ldbw, m0, n0, 16);
    CP_COMMIT();
    issue_stage(smu, 2, Ahp, ldaw, A2h, kspw, Bhp, ldbw, m0, n0, 32);
    CP_COMMIT();

    for (int kt = 0; kt < nK; kt++) {
        CP_WAIT2();
        __syncthreads();
        if (kt + 3 < nK) {
            issue_stage(smu, (kt + 3) & 3, Ahp, ldaw, A2h, kspw, Bhp, ldbw,
                        m0, n0, (kt + 3) * 16);
            CP_COMMIT();
        }
        mma_stage(sm + (kt & 3) * 5120, wm, wn, g, t, acc);
    }
}

// ---------------------------------------------------------------------------
// Kernel 1: gate (z=0, longest first) + 5 projections (z=1..5).
// Q written pre-scaled by 1/sqrt(128).
// ---------------------------------------------------------------------------
__global__ __launch_bounds__(256, 2) void projgate_kernel(
    const float* __restrict__ bqa, const float* __restrict__ bqg,
    const float* __restrict__ bka, const float* __restrict__ bkg,
    const float* __restrict__ bva, const float* __restrict__ bgate)
{
    extern __shared__ uint32_t sm[];
    const int m0 = blockIdx.y * 128;
    const int n0 = blockIdx.x * 128;
    const int lane = threadIdx.x & 31, warp = threadIdx.x >> 5;
    const int wm = (warp & 3) * 32, wn = (warp >> 2) * 64;
    const int g = lane >> 2, t = lane & 3;
    float acc[2][8][4] = {};

    if (blockIdx.z == 0) {
        gemm_fp16_ca(sm, g_INh, 512, g_INh + 2097152, 512,
                     g_Wh + OW_GATE, 1024, 1024, m0, n0, acc);

        #pragma unroll
        for (int nf = 0; nf < 8; nf++) {
            const int n = n0 + wn + nf * 8 + 2 * t;
            const float bx = bgate[n], by = bgate[n + 1];
            #pragma unroll
            for (int mt = 0; mt < 2; mt++) {
                #pragma unroll
                for (int h2 = 0; h2 < 2; h2++) {
                    const int m = m0 + wm + mt * 16 + g + h2 * 8;
                    float2 v;
                    v.x = 1.0f / (1.0f + __expf(-(acc[mt][nf][h2 * 2 + 0] + bx)));
                    v.y = 1.0f / (1.0f + __expf(-(acc[mt][nf][h2 * 2 + 1] + by)));
                    *(float2*)&g_G[(size_t)m * 1024 + n] = v;
                }
            }
        }
    } else {
        const int p = blockIdx.z - 1;
        const uint32_t* Ahp = g_INh + (size_t)p * 2097152;
        const uint32_t woff = (p == 0) ? OW_QA : (p == 1) ? OW_QG : (p == 2) ? OW_KA
                            : (p == 3) ? OW_KG : OW_VA;
        const float* bias = (p == 0) ? bqa : (p == 1) ? bqg : (p == 2) ? bka
                          : (p == 3) ? bkg : bva;
        gemm_fp16_ca(sm, Ahp, 512, nullptr, 1 << 30, g_Wh + woff, 512, 512, m0, n0, acc);

        const float qs = (p < 2) ? 0.08838834764831845f : 1.0f;
        #pragma unroll
        for (int nf = 0; nf < 8; nf++) {
            const int n  = n0 + wn + nf * 8 + 2 * t;
            const int h  = n >> 6, jj = n & 63;
            const float bx = bias[n], by = bias[n + 1];
            #pragma unroll
            for (int mt = 0; mt < 2; mt++) {
                #pragma unroll
                for (int h2 = 0; h2 < 2; h2++) {
                    const int m = m0 + wm + mt * 16 + g + h2 * 8;
                    const int b = m >> 10, s = m & 1023;
                    const size_t bhh = (size_t)(b * 16 + h);
                    const float vx = (acc[mt][nf][h2 * 2 + 0] + bx) * qs;
                    const float vy = (acc[mt][nf][h2 * 2 + 1] + by) * qs;
                    if (p == 4) {
                        __half* Vp = (__half*)g_Vh;
                        Vp[(bhh * 64 + jj)     * 1024 + s] = __float2half_rn(vx);
                        Vp[(bhh * 64 + jj + 1) * 1024 + s] = __float2half_rn(vy);
                    } else {
                        const size_t widx = (bhh * 1024 + s) * 64 + ((p & 1) ? 32 : 0) + (jj >> 1);
                        if (p < 2) g_Qh[widx] = pack_h2(vx, vy);
                        else       g_Kh[widx] = pack_h2(vx, vy);
                    }
                }
            }
        }
    }
}

// ---------------------------------------------------------------------------
// Kernel 3: fused flash attention (R13 version — online max, 3 barriers/tile).
// smem: Qh [128][68] @0, Kst0 @34816, Kst1 @69632, Vst0 @104448, Vst1 @121856,
// redmax @139264, redsum @140288. Osum reuses Kst0.
// ---------------------------------------------------------------------------
#define ATTN_SMEM 141312

__global__ __launch_bounds__(256) void attn_kernel()
{
    extern __shared__ char smem[];
    uint32_t (*Qh)[68] = (uint32_t(*)[68])(smem);
    float* redmax = (float*)(smem + 139264);
    float* redsum = (float*)(smem + 140288);
    float* Osum   = (float*)(smem + 34816);
    const uint32_t smu = smem_u32(smem);

    const int tid  = threadIdx.x;
    const int warp = tid >> 5, lane = tid & 31;
    const int wm = (warp & 3) * 32;
    const int wn = (warp >> 2);
    const int g  = lane >> 2;
    const int t  = lane & 3;

    const int bh = blockIdx.y;
    const int b  = bh >> 4, h = bh & 15;
    const int m0 = blockIdx.x * 128;

    const uint32_t* Qhg = g_Qh + ((size_t)bh << 16);
    const uint32_t* Khg = g_Kh + ((size_t)bh << 16);
    const uint32_t* Vhg = g_Vh + (size_t)bh * 32768;

    const int lr16 = tid >> 4;
    const int cw4  = (tid & 15) * 4;

    // Q tile (once)
    {
        const int lrow = tid >> 5;
        const int pcw  = (tid & 31) * 2;
        #pragma unroll
        for (int i = 0; i < 16; i++) {
            const int r = lrow + i * 8;
            *(uint2*)&Qh[r][pcw] = *(const uint2*)(Qhg + (size_t)(m0 + r) * 64 + pcw);
        }
    }

    auto issue_kv = [&](int nt, int st) {
        const int n0 = nt * 128;
        const uint32_t kbase = smu + 34816u + (uint32_t)st * 34816u;
        const uint32_t vbase = smu + 104448u + (uint32_t)st * 17408u;
        #pragma unroll
        for (int i = 0; i < 8; i++) {
            const int r = lr16 + i * 16;
            cp16(kbase + (uint32_t)((r * 68 + cw4) * 4),
                 Khg + (size_t)(n0 + r) * 64 + cw4);
        }
        #pragma unroll
        for (int i = 0; i < 4; i++) {
            const int r = lr16 + i * 16;
            cp16(vbase + (uint32_t)((r * 68 + cw4) * 4),
                 Vhg + (size_t)r * 512 + (n0 >> 1) + cw4);
        }
        CP_COMMIT();
    };

    float o[2][8][4] = {};
    float mrun[2][2] = {{-INFINITY, -INFINITY}, {-INFINITY, -INFINITY}};
    float lrun[2][2] = {};

    issue_kv(0, 0);

    for (int nt = 0; nt < 8; nt++) {
        CP_WAIT0();
        __syncthreads();
        if (nt + 1 < 8)
            issue_kv(nt + 1, (nt + 1) & 1);

        const int st = nt & 1;
        uint32_t (*Kh)[68] = (uint32_t(*)[68])(smem + 34816 + st * 34816);
        uint32_t (*Vh)[68] = (uint32_t(*)[68])(smem + 104448 + st * 17408);
        const int n0 = nt * 128;

        // ---- S = Q K^T (Q pre-scaled) ----
        float s[2][8][4] = {};
        #pragma unroll
        for (int ks = 0; ks < 8; ks++) {
            const int pc = ks * 8;
            uint32_t ah[2][4];
            #pragma unroll
            for (int mt = 0; mt < 2; mt++) {
                #pragma unroll
                for (int q = 0; q < 4; q++) {
                    const int row = wm + mt * 16 + g + (q & 1) * 8;
                    const int col = pc + t + (q >> 1) * 4;
                    ah[mt][q] = Qh[row][col];
                }
            }
            #pragma unroll
            for (int nf = 0; nf < 8; nf++) {
                const int rb = wn * 64 + nf * 8 + g;
                const uint32_t b0 = Kh[rb][pc + t], b1 = Kh[rb][pc + t + 4];
                #pragma unroll
                for (int mt = 0; mt < 2; mt++)
                    mma_fp16(s[mt][nf], ah[mt][0], ah[mt][1], ah[mt][2], ah[mt][3], b0, b1);
            }
        }

        // ---- + mask bias + row max ----
        float pm[2][2];
        #pragma unroll
        for (int mt = 0; mt < 2; mt++) {
            #pragma unroll
            for (int h2 = 0; h2 < 2; h2++) {
                const int rglob = m0 + wm + mt * 16 + g + h2 * 8;
                float mx = -INFINITY;
                #pragma unroll
                for (int nf = 0; nf < 8; nf++) {
                    const int ncol = n0 + wn * 64 + nf * 8 + 2 * t;
                    const uint32_t mb = g_MB[((size_t)b << 19) + ((size_t)rglob << 9) + (ncol >> 1)];
                    const float2 bias = __half22float2(*(const __half2*)&mb);
                    float v0 = s[mt][nf][h2 * 2 + 0] + bias.x;
                    float v1 = s[mt][nf][h2 * 2 + 1] + bias.y;
                    s[mt][nf][h2 * 2 + 0] = v0;
                    s[mt][nf][h2 * 2 + 1] = v1;
                    mx = fmaxf(mx, fmaxf(v0, v1));
                }
                pm[mt][h2] = mx;
            }
        }
        #pragma unroll
        for (int mt = 0; mt < 2; mt++)
            #pragma unroll
            for (int h2 = 0; h2 < 2; h2++) {
                pm[mt][h2] = fmaxf(pm[mt][h2], __shfl_xor_sync(0xffffffffu, pm[mt][h2], 1));
                pm[mt][h2] = fmaxf(pm[mt][h2], __shfl_xor_sync(0xffffffffu, pm[mt][h2], 2));
            }
        if (t == 0) {
            #pragma unroll
            for (int mt = 0; mt < 2; mt++)
                #pragma unroll
                for (int h2 = 0; h2 < 2; h2++)
                    redmax[wn * 128 + wm + mt * 16 + g + h2 * 8] = pm[mt][h2];
        }
        __syncthreads();

        // ---- running stats, exponentiate, rescale O ----
        float alpha[2][2], psum[2][2];
        #pragma unroll
        for (int mt = 0; mt < 2; mt++) {
            #pragma unroll
            for (int h2 = 0; h2 < 2; h2++) {
                const int rl = wm + mt * 16 + g + h2 * 8;
                const float mtile = fmaxf(redmax[rl], redmax[128 + rl]);
                const float mnew  = fmaxf(mrun[mt][h2], mtile);
                alpha[mt][h2] = __expf(mrun[mt][h2] - mnew);
                mrun[mt][h2]  = mnew;
                float ps = 0.0f;
                #pragma unroll
                for (int nf = 0; nf < 8; nf++) {
                    float p0 = __expf(s[mt][nf][h2 * 2 + 0] - mnew);
                    float p1 = __expf(s[mt][nf][h2 * 2 + 1] - mnew);
                    s[mt][nf][h2 * 2 + 0] = p0;
                    s[mt][nf][h2 * 2 + 1] = p1;
                    ps += p0 + p1;
                }
                psum[mt][h2] = ps;
            }
        }
        #pragma unroll
        for (int mt = 0; mt < 2; mt++)
            #pragma unroll
            for (int nf = 0; nf < 8; nf++)
                #pragma unroll
                for (int e = 0; e < 4; e++)
                    o[mt][nf][e] *= alpha[mt][e >> 1];
        #pragma unroll
        for (int mt = 0; mt < 2; mt++)
            #pragma unroll
            for (int h2 = 0; h2 < 2; h2++) {
                psum[mt][h2] += __shfl_xor_sync(0xffffffffu, psum[mt][h2], 1);
                psum[mt][h2] += __shfl_xor_sync(0xffffffffu, psum[mt][h2], 2);
            }
        if (t == 0) {
            #pragma unroll
            for (int mt = 0; mt < 2; mt++)
                #pragma unroll
                for (int h2 = 0; h2 < 2; h2++)
                    redsum[wn * 128 + wm + mt * 16 + g + h2 * 8] = psum[mt][h2];
        }
        __syncthreads();
        #pragma unroll
        for (int mt = 0; mt < 2; mt++)
            #pragma unroll
            for (int h2 = 0; h2 < 2; h2++) {
                const int rl = wm + mt * 16 + g + h2 * 8;
                lrun[mt][h2] = lrun[mt][h2] * alpha[mt][h2] + redsum[rl] + redsum[128 + rl];
            }

        // ---- O += P V ----
        #pragma unroll
        for (int ks2 = 0; ks2 < 4; ks2++) {
            uint32_t ah[2][4];
            #pragma unroll
            for (int mt = 0; mt < 2; mt++) {
                ah[mt][0] = pack_h2(s[mt][2 * ks2][0],     s[mt][2 * ks2][1]);
                ah[mt][1] = pack_h2(s[mt][2 * ks2][2],     s[mt][2 * ks2][3]);
                ah[mt][2] = pack_h2(s[mt][2 * ks2 + 1][0], s[mt][2 * ks2 + 1][1]);
                ah[mt][3] = pack_h2(s[mt][2 * ks2 + 1][2], s[mt][2 * ks2 + 1][3]);
            }
            const int vcol = wn * 32 + ks2 * 8 + t;
            #pragma unroll
            for (int nf = 0; nf < 8; nf++) {
                const int rv = nf * 8 + g;
                const uint32_t b0 = Vh[rv][vcol], b1 = Vh[rv][vcol + 4];
                #pragma unroll
                for (int mt = 0; mt < 2; mt++)
                    mma_fp16(o[mt][nf], ah[mt][0], ah[mt][1], ah[mt][2], ah[mt][3], b0, b1);
            }
        }
    }

    // ---- epilogue ----
    __syncthreads();
    if (wn == 1) {
        #pragma unroll
        for (int mt = 0; mt < 2; mt++)
            #pragma unroll
            for (int h2 = 0; h2 < 2; h2++) {
                const int rl = wm + mt * 16 + g + h2 * 8;
                #pragma unroll
                for (int nf = 0; nf < 8; nf++) {
                    float2 v;
                    v.x = o[mt][nf][h2 * 2 + 0];
                    v.y = o[mt][nf][h2 * 2 + 1];
                    *(float2*)&Osum[rl * 66 + nf * 8 + 2 * t] = v;
                }
            }
    }
    __syncthreads();
    if (wn == 0) {
        #pragma unroll
        for (int mt = 0; mt < 2; mt++)
            #pragma unroll
            for (int h2 = 0; h2 < 2; h2++) {
                const int rl = wm + mt * 16 + g + h2 * 8;
                const float inv = 1.0f / lrun[mt][h2];
                #pragma unroll
                for (int nf = 0; nf < 8; nf++) {
                    const int c = nf * 8 + 2 * t;
                    float2 p = *(float2*)&Osum[rl * 66 + c];
                    const float vx = (o[mt][nf][h2 * 2 + 0] + p.x) * inv;
                    const float vy = (o[mt][nf][h2 * 2 + 1] + p.y) * inv;
                    g_Xh[(size_t)(b * 1024 + m0 + rl) * 512 + ((h * 64 + c) >> 1)] = pack_h2(vx, vy);
                }
            }
    }
}

// ---------------------------------------------------------------------------
// Kernel 4: out = gate * (X @ Winfo^T + binfo)
// ---------------------------------------------------------------------------
__global__ __launch_bounds__(256, 2) void info_kernel(
    const float* __restrict__ binfo, float* __restrict__ out)
{
    extern __shared__ uint32_t sm[];
    const int m0 = blockIdx.y * 128;
    const int n0 = blockIdx.x * 128;
    float acc[2][8][4] = {};
    gemm_fp16_ca(sm, g_Xh, 512, nullptr, 1 << 30, g_Wh + OW_INFO, 512, 512, m0, n0, acc);

    const int lane = threadIdx.x & 31, warp = threadIdx.x >> 5;
    const int wm = (warp & 3) * 32, wn = (warp >> 2) * 64;
    const int g = lane >> 2, t = lane & 3;

    #pragma unroll
    for (int nf = 0; nf < 8; nf++) {
        const int n = n0 + wn + nf * 8 + 2 * t;
        const float bx = binfo[n], by = binfo[n + 1];
        #pragma unroll
        for (int mt = 0; mt < 2; mt++) {
            #pragma unroll
            for (int h2 = 0; h2 < 2; h2++) {
                const int m = m0 + wm + mt * 16 + g + h2 * 8;
                const float2 gg = *(const float2*)&g_G[(size_t)m * 1024 + n];
                float2 v;
                v.x = gg.x * (acc[mt][nf][h2 * 2 + 0] + bx);
                v.y = gg.y * (acc[mt][nf][h2 * 2 + 1] + by);
                *(float2*)&out[(size_t)m * 1024 + n] = v;
            }
        }
    }
}

// ---------------------------------------------------------------------------
extern "C" void kernel_launch(void* const* d_in, const int* in_sizes, int n_in,
                              void* d_out, int out_size)
{
    (void)in_sizes; (void)n_in; (void)out_size;
    const float* query_g = (const float*)d_in[0];
    const float* key_g   = (const float*)d_in[1];
    const float* query_a = (const float*)d_in[2];
    const float* key_a   = (const float*)d_in[3];
    const float* value_a = (const float*)d_in[4];
    const int*   mask    = (const int*)  d_in[5];
    const float* Wqg = (const float*)d_in[6];  const float* bqg = (const float*)d_in[7];
    const float* Wkg = (const float*)d_in[8];  const float* bkg = (const float*)d_in[9];
    const float* Wqa = (const float*)d_in[10]; const float* bqa = (const float*)d_in[11];
    const float* Wka = (const float*)d_in[12]; const float* bka = (const float*)d_in[13];
    const float* Wva = (const float*)d_in[14]; const float* bva = (const float*)d_in[15];
    const float* Wgate = (const float*)d_in[16]; const float* bgate = (const float*)d_in[17];
    const float* Winfo = (const float*)d_in[18]; const float* binfo = (const float*)d_in[19];

    static int attr_set = 0;
    if (!attr_set) {
        cudaFuncSetAttribute(attn_kernel, cudaFuncAttributeMaxDynamicSharedMemorySize, ATTN_SMEM);
        cudaFuncSetAttribute(projgate_kernel, cudaFuncAttributeMaxDynamicSharedMemorySize, GSMEM);
        cudaFuncSetAttribute(info_kernel, cudaFuncAttributeMaxDynamicSharedMemorySize, GSMEM);
        attr_set = 1;
    }

    dim3 blk(256);
    conv_all_kernel<<<dim3(4096, 13), blk>>>(query_g, key_g, query_a, key_a, value_a,
                                             Wqa, Wqg, Wka, Wkg, Wva, Wgate, Winfo, mask);
    projgate_kernel<<<dim3(8, 32, 6), blk, GSMEM>>>(bqa, bqg, bka, bkg, bva, bgate);
    attn_kernel<<<dim3(8, 64), blk, ATTN_SMEM>>>();
    info_kernel<<<dim3(8, 32, 1), blk, GSMEM>>>(binfo, (float*)d_out);
}

// round 16
// speedup vs baseline: 1.0449x; 1.0166x over previous
#include <cuda_runtime.h>
#include <cuda_fp16.h>
#include <math.h>
#include <stdint.h>

// Problem constants
#define B_  4
#define S_  1024
#define BH  64     // B*H

// ---------------------------------------------------------------------------
// Scratch. "h" arrays hold packed fp16 pairs: word w = h(x[2w]) | h(x[2w+1])<<16
// ---------------------------------------------------------------------------
static __device__ uint32_t g_INh[(size_t)5 * 2097152];   // [qa,qg,ka,kg,va] inputs
static __device__ uint32_t g_Wh[(size_t)4194304];        // Wqa..Wva,Wgate,Winfo
static __device__ uint32_t g_Qh[(size_t)BH * S_ * 64];   // [bh,s,64w] (qa|qg), pre-scaled
static __device__ uint32_t g_Kh[(size_t)BH * S_ * 64];
static __device__ uint32_t g_Vh[(size_t)BH * 64 * 512];  // transposed [bh,j,s] fp16
static __device__ uint32_t g_MB[(size_t)B_ * S_ * 512];  // mask bias packed fp16 (0 / -30000)
static __device__ uint32_t g_Xh[(size_t)4096 * 512];     // attn out packed
static __device__ uint32_t g_Gh[(size_t)4096 * 512];     // gate packed fp16

#define OW_QA 0u
#define OW_QG 524288u
#define OW_KA 1048576u
#define OW_KG 1572864u
#define OW_VA 2097152u
#define OW_GATE 2621440u
#define OW_INFO 3670016u

// ---------------------------------------------------------------------------
__device__ __forceinline__ uint32_t pack_h2(float x, float y) {
    __half2 h = __floats2half2_rn(x, y);
    return *(uint32_t*)&h;
}

__device__ __forceinline__ void mma_fp16(float* c,
    uint32_t a0, uint32_t a1, uint32_t a2, uint32_t a3,
    uint32_t b0, uint32_t b1)
{
    asm volatile(
        "mma.sync.aligned.m16n8k16.row.col.f32.f16.f16.f32 "
        "{%0,%1,%2,%3},{%4,%5,%6,%7},{%8,%9},{%0,%1,%2,%3};"
        : "+f"(c[0]), "+f"(c[1]), "+f"(c[2]), "+f"(c[3])
        : "r"(a0), "r"(a1), "r"(a2), "r"(a3), "r"(b0), "r"(b1));
}

__device__ __forceinline__ uint32_t smem_u32(const void* p) {
    uint32_t a;
    asm("{ .reg .u64 t; cvta.to.shared.u64 t, %1; cvt.u32.u64 %0, t; }" : "=r"(a) : "l"(p));
    return a;
}

__device__ __forceinline__ void cp16(uint32_t dst, const void* src) {
    asm volatile("cp.async.ca.shared.global [%0], [%1], 16;" :: "r"(dst), "l"(src));
}
#define CP_COMMIT() asm volatile("cp.async.commit_group;" ::: "memory")
#define CP_WAIT1()  asm volatile("cp.async.wait_group 1;" ::: "memory")
#define CP_WAIT0()  asm volatile("cp.async.wait_group 0;" ::: "memory")

// ---------------------------------------------------------------------------
// Merged conversion kernel. grid = (4096, 13).
// ---------------------------------------------------------------------------
__global__ __launch_bounds__(256) void conv_all_kernel(
    const float* __restrict__ q_g, const float* __restrict__ k_g,
    const float* __restrict__ q_a, const float* __restrict__ k_a,
    const float* __restrict__ v_a,
    const float* __restrict__ Wqa, const float* __restrict__ Wqg,
    const float* __restrict__ Wka, const float* __restrict__ Wkg,
    const float* __restrict__ Wva, const float* __restrict__ Wgate,
    const float* __restrict__ Winfo,
    const int* __restrict__ mask)
{
    const int z = blockIdx.y;
    const size_t i = (size_t)blockIdx.x * 256 + threadIdx.x;

    if (z < 5) {
        const float* src = (z == 0) ? q_a : (z == 1) ? q_g : (z == 2) ? k_a
                         : (z == 3) ? k_g : v_a;
        float4 v = ((const float4*)src)[i];
        const size_t w = (size_t)z * 2097152 + i * 2;
        g_INh[w]     = pack_h2(v.x, v.y);
        g_INh[w + 1] = pack_h2(v.z, v.w);
    } else if (z < 12) {
        const int wz = z - 5;
        const float* src; size_t offw; size_t nf4;
        switch (wz) {
            case 0: src = Wqa;   offw = OW_QA;   nf4 = 262144; break;
            case 1: src = Wqg;   offw = OW_QG;   nf4 = 262144; break;
            case 2: src = Wka;   offw = OW_KA;   nf4 = 262144; break;
            case 3: src = Wkg;   offw = OW_KG;   nf4 = 262144; break;
            case 4: src = Wva;   offw = OW_VA;   nf4 = 262144; break;
            case 5: src = Wgate; offw = OW_GATE; nf4 = 524288; break;
            default: src = Winfo; offw = OW_INFO; nf4 = 262144; break;
        }
        if (i < nf4) {
            float4 v = ((const float4*)src)[i];
            const size_t w = offw + i * 2;
            g_Wh[w]     = pack_h2(v.x, v.y);
            g_Wh[w + 1] = pack_h2(v.z, v.w);
        }
    } else {
        #pragma unroll
        for (int r = 0; r < 2; r++) {
            const size_t j = i + (size_t)r * 1048576;
            const int2 mk = ((const int2*)mask)[j];
            g_MB[j] = pack_h2(mk.x == 0 ? -30000.0f : 0.0f,
                              mk.y == 0 ? -30000.0f : 0.0f);
        }
    }
}

// ---------------------------------------------------------------------------
// fp16 GEMM via cp.async 3-stage pipeline (R13 config).
// Stage: A [128][20]w @ +0, B [128][20]w @ +2560w. Stage stride 5120 words.
// ---------------------------------------------------------------------------
#define GSMEM 61440
typedef uint32_t (*SmT)[20];

__device__ __forceinline__ void issue_stage(
    uint32_t smu, int stage,
    const uint32_t* __restrict__ Ahp, int ldaw,
    const uint32_t* __restrict__ A2h, int kspw,
    const uint32_t* __restrict__ Bhp, int ldbw,
    int m0, int n0, int kw0)
{
    const int tid = threadIdx.x;
    const uint32_t sbase = smu + (uint32_t)stage * 20480u;
    #pragma unroll
    for (int c = 0; c < 2; c++) {
        const int cid = tid + c * 256;
        const int row = cid >> 2, cw = (cid & 3) << 2;
        const int gw = kw0 + cw;
        const uint32_t* srcA;
        if (gw >= kspw) srcA = A2h + (size_t)(m0 + row) * 512 + (gw - kspw);
        else            srcA = Ahp + (size_t)(m0 + row) * ldaw + gw;
        const uint32_t dstA = sbase + (uint32_t)((row * 20 + cw) * 4);
        cp16(dstA, srcA);
        cp16(dstA + 10240u, Bhp + (size_t)(n0 + row) * ldbw + gw);
    }
}

__device__ __forceinline__ void mma_stage(
    uint32_t* stg, int wm, int wn, int g, int t, float acc[2][8][4])
{
    SmT Ah = (SmT)stg;
    SmT Bh = (SmT)(stg + 2560);
    #pragma unroll
    for (int kk = 0; kk < 2; kk++) {
        const int pc = kk * 8;
        uint32_t ah[2][4];
        #pragma unroll
        for (int mt = 0; mt < 2; mt++) {
            #pragma unroll
            for (int q = 0; q < 4; q++) {
                const int row = wm + mt * 16 + g + (q & 1) * 8;
                const int col = pc + t + (q >> 1) * 4;
                ah[mt][q] = Ah[row][col];
            }
        }
        #pragma unroll
        for (int nf = 0; nf < 8; nf++) {
            const int rb = wn + nf * 8 + g;
            const uint32_t b0 = Bh[rb][pc + t], b1 = Bh[rb][pc + t + 4];
            #pragma unroll
            for (int mt = 0; mt < 2; mt++)
                mma_fp16(acc[mt][nf], ah[mt][0], ah[mt][1], ah[mt][2], ah[mt][3], b0, b1);
        }
    }
}

__device__ __forceinline__ void gemm_fp16_ca(
    uint32_t* sm,
    const uint32_t* __restrict__ Ahp, int ldaw,
    const uint32_t* __restrict__ A2h, int kspw,
    const uint32_t* __restrict__ Bhp, int ldbw,
    int Kw, int m0, int n0, float acc[2][8][4])
{
    const uint32_t smu = smem_u32(sm);
    const int warp = threadIdx.x >> 5, lane = threadIdx.x & 31;
    const int wm = (warp & 3) * 32, wn = (warp >> 2) * 64;
    const int g = lane >> 2, t = lane & 3;
    const int nK = Kw >> 4;

    issue_stage(smu, 0, Ahp, ldaw, A2h, kspw, Bhp, ldbw, m0, n0, 0);
    CP_COMMIT();
    issue_stage(smu, 1, Ahp, ldaw, A2h, kspw, Bhp, ldbw, m0, n0, 16);
    CP_COMMIT();

    for (int kt = 0; kt < nK; kt++) {
        CP_WAIT1();
        __syncthreads();
        if (kt + 2 < nK) {
            issue_stage(smu, (kt + 2) % 3, Ahp, ldaw, A2h, kspw, Bhp, ldbw,
                        m0, n0, (kt + 2) * 16);
            CP_COMMIT();
        }
        mma_stage(sm + (kt % 3) * 5120, wm, wn, g, t, acc);
    }
}

// ---------------------------------------------------------------------------
// Kernel 1: gate (z=0, longest first) + 5 projections (z=1..5).
// Q written pre-scaled by 1/sqrt(128). Gate stored packed fp16.
// ---------------------------------------------------------------------------
__global__ __launch_bounds__(256, 2) void projgate_kernel(
    const float* __restrict__ bqa, const float* __restrict__ bqg,
    const float* __restrict__ bka, const float* __restrict__ bkg,
    const float* __restrict__ bva, const float* __restrict__ bgate)
{
    extern __shared__ uint32_t sm[];
    const int m0 = blockIdx.y * 128;
    const int n0 = blockIdx.x * 128;
    const int lane = threadIdx.x & 31, warp = threadIdx.x >> 5;
    const int wm = (warp & 3) * 32, wn = (warp >> 2) * 64;
    const int g = lane >> 2, t = lane & 3;
    float acc[2][8][4] = {};

    if (blockIdx.z == 0) {
        gemm_fp16_ca(sm, g_INh, 512, g_INh + 2097152, 512,
                     g_Wh + OW_GATE, 1024, 1024, m0, n0, acc);

        #pragma unroll
        for (int nf = 0; nf < 8; nf++) {
            const int n = n0 + wn + nf * 8 + 2 * t;
            const float bx = bgate[n], by = bgate[n + 1];
            #pragma unroll
            for (int mt = 0; mt < 2; mt++) {
                #pragma unroll
                for (int h2 = 0; h2 < 2; h2++) {
                    const int m = m0 + wm + mt * 16 + g + h2 * 8;
                    const float gx = 1.0f / (1.0f + __expf(-(acc[mt][nf][h2 * 2 + 0] + bx)));
                    const float gy = 1.0f / (1.0f + __expf(-(acc[mt][nf][h2 * 2 + 1] + by)));
                    g_Gh[(size_t)m * 512 + (n >> 1)] = pack_h2(gx, gy);
                }
            }
        }
    } else {
        const int p = blockIdx.z - 1;
        const uint32_t* Ahp = g_INh + (size_t)p * 2097152;
        const uint32_t woff = (p == 0) ? OW_QA : (p == 1) ? OW_QG : (p == 2) ? OW_KA
                            : (p == 3) ? OW_KG : OW_VA;
        const float* bias = (p == 0) ? bqa : (p == 1) ? bqg : (p == 2) ? bka
                          : (p == 3) ? bkg : bva;
        gemm_fp16_ca(sm, Ahp, 512, nullptr, 1 << 30, g_Wh + woff, 512, 512, m0, n0, acc);

        const float qs = (p < 2) ? 0.08838834764831845f : 1.0f;
        #pragma unroll
        for (int nf = 0; nf < 8; nf++) {
            const int n  = n0 + wn + nf * 8 + 2 * t;
            const int h  = n >> 6, jj = n & 63;
            const float bx = bias[n], by = bias[n + 1];
            #pragma unroll
            for (int mt = 0; mt < 2; mt++) {
                #pragma unroll
                for (int h2 = 0; h2 < 2; h2++) {
                    const int m = m0 + wm + mt * 16 + g + h2 * 8;
                    const int b = m >> 10, s = m & 1023;
                    const size_t bhh = (size_t)(b * 16 + h);
                    const float vx = (acc[mt][nf][h2 * 2 + 0] + bx) * qs;
                    const float vy = (acc[mt][nf][h2 * 2 + 1] + by) * qs;
                    if (p == 4) {
                        __half* Vp = (__half*)g_Vh;
                        Vp[(bhh * 64 + jj)     * 1024 + s] = __float2half_rn(vx);
                        Vp[(bhh * 64 + jj + 1) * 1024 + s] = __float2half_rn(vy);
                    } else {
                        const size_t widx = (bhh * 1024 + s) * 64 + ((p & 1) ? 32 : 0) + (jj >> 1);
                        if (p < 2) g_Qh[widx] = pack_h2(vx, vy);
                        else       g_Kh[widx] = pack_h2(vx, vy);
                    }
                }
            }
        }
    }
}

// ---------------------------------------------------------------------------
// Kernel 3: fused flash attention (R13 version).
// smem: Qh [128][68] @0, Kst0 @34816, Kst1 @69632, Vst0 @104448, Vst1 @121856,
// redmax @139264, redsum @140288. Osum reuses Kst0.
// ---------------------------------------------------------------------------
#define ATTN_SMEM 141312

__global__ __launch_bounds__(256) void attn_kernel()
{
    extern __shared__ char smem[];
    uint32_t (*Qh)[68] = (uint32_t(*)[68])(smem);
    float* redmax = (float*)(smem + 139264);
    float* redsum = (float*)(smem + 140288);
    float* Osum   = (float*)(smem + 34816);
    const uint32_t smu = smem_u32(smem);

    const int tid  = threadIdx.x;
    const int warp = tid >> 5, lane = tid & 31;
    const int wm = (warp & 3) * 32;
    const int wn = (warp >> 2);
    const int g  = lane >> 2;
    const int t  = lane & 3;

    const int bh = blockIdx.y;
    const int b  = bh >> 4, h = bh & 15;
    const int m0 = blockIdx.x * 128;

    const uint32_t* Qhg = g_Qh + ((size_t)bh << 16);
    const uint32_t* Khg = g_Kh + ((size_t)bh << 16);
    const uint32_t* Vhg = g_Vh + (size_t)bh * 32768;

    const int lr16 = tid >> 4;
    const int cw4  = (tid & 15) * 4;

    {
        const int lrow = tid >> 5;
        const int pcw  = (tid & 31) * 2;
        #pragma unroll
        for (int i = 0; i < 16; i++) {
            const int r = lrow + i * 8;
            *(uint2*)&Qh[r][pcw] = *(const uint2*)(Qhg + (size_t)(m0 + r) * 64 + pcw);
        }
    }

    auto issue_kv = [&](int nt, int st) {
        const int n0 = nt * 128;
        const uint32_t kbase = smu + 34816u + (uint32_t)st * 34816u;
        const uint32_t vbase = smu + 104448u + (uint32_t)st * 17408u;
        #pragma unroll
        for (int i = 0; i < 8; i++) {
            const int r = lr16 + i * 16;
            cp16(kbase + (uint32_t)((r * 68 + cw4) * 4),
                 Khg + (size_t)(n0 + r) * 64 + cw4);
        }
        #pragma unroll
        for (int i = 0; i < 4; i++) {
            const int r = lr16 + i * 16;
            cp16(vbase + (uint32_t)((r * 68 + cw4) * 4),
                 Vhg + (size_t)r * 512 + (n0 >> 1) + cw4);
        }
        CP_COMMIT();
    };

    float o[2][8][4] = {};
    float mrun[2][2] = {{-INFINITY, -INFINITY}, {-INFINITY, -INFINITY}};
    float lrun[2][2] = {};

    issue_kv(0, 0);

    for (int nt = 0; nt < 8; nt++) {
        CP_WAIT0();
        __syncthreads();
        if (nt + 1 < 8)
            issue_kv(nt + 1, (nt + 1) & 1);

        const int st = nt & 1;
        uint32_t (*Kh)[68] = (uint32_t(*)[68])(smem + 34816 + st * 34816);
        uint32_t (*Vh)[68] = (uint32_t(*)[68])(smem + 104448 + st * 17408);
        const int n0 = nt * 128;

        float s[2][8][4] = {};
        #pragma unroll
        for (int ks = 0; ks < 8; ks++) {
            const int pc = ks * 8;
            uint32_t ah[2][4];
            #pragma unroll
            for (int mt = 0; mt < 2; mt++) {
                #pragma unroll
                for (int q = 0; q < 4; q++) {
                    const int row = wm + mt * 16 + g + (q & 1) * 8;
                    const int col = pc + t + (q >> 1) * 4;
                    ah[mt][q] = Qh[row][col];
                }
            }
            #pragma unroll
            for (int nf = 0; nf < 8; nf++) {
                const int rb = wn * 64 + nf * 8 + g;
                const uint32_t b0 = Kh[rb][pc + t], b1 = Kh[rb][pc + t + 4];
                #pragma unroll
                for (int mt = 0; mt < 2; mt++)
                    mma_fp16(s[mt][nf], ah[mt][0], ah[mt][1], ah[mt][2], ah[mt][3], b0, b1);
            }
        }

        float pm[2][2];
        #pragma unroll
        for (int mt = 0; mt < 2; mt++) {
            #pragma unroll
            for (int h2 = 0; h2 < 2; h2++) {
                const int rglob = m0 + wm + mt * 16 + g + h2 * 8;
                float mx = -INFINITY;
                #pragma unroll
                for (int nf = 0; nf < 8; nf++) {
                    const int ncol = n0 + wn * 64 + nf * 8 + 2 * t;
                    const uint32_t mb = g_MB[((size_t)b << 19) + ((size_t)rglob << 9) + (ncol >> 1)];
                    const float2 bias = __half22float2(*(const __half2*)&mb);
                    float v0 = s[mt][nf][h2 * 2 + 0] + bias.x;
                    float v1 = s[mt][nf][h2 * 2 + 1] + bias.y;
                    s[mt][nf][h2 * 2 + 0] = v0;
                    s[mt][nf][h2 * 2 + 1] = v1;
                    mx = fmaxf(mx, fmaxf(v0, v1));
                }
                pm[mt][h2] = mx;
            }
        }
        #pragma unroll
        for (int mt = 0; mt < 2; mt++)
            #pragma unroll
            for (int h2 = 0; h2 < 2; h2++) {
                pm[mt][h2] = fmaxf(pm[mt][h2], __shfl_xor_sync(0xffffffffu, pm[mt][h2], 1));
                pm[mt][h2] = fmaxf(pm[mt][h2], __shfl_xor_sync(0xffffffffu, pm[mt][h2], 2));
            }
        if (t == 0) {
            #pragma unroll
            for (int mt = 0; mt < 2; mt++)
                #pragma unroll
                for (int h2 = 0; h2 < 2; h2++)
                    redmax[wn * 128 + wm + mt * 16 + g + h2 * 8] = pm[mt][h2];
        }
        __syncthreads();

        float alpha[2][2], psum[2][2];
        #pragma unroll
        for (int mt = 0; mt < 2; mt++) {
            #pragma unroll
            for (int h2 = 0; h2 < 2; h2++) {
                const int rl = wm + mt * 16 + g + h2 * 8;
                const float mtile = fmaxf(redmax[rl], redmax[128 + rl]);
                const float mnew  = fmaxf(mrun[mt][h2], mtile);
                alpha[mt][h2] = __expf(mrun[mt][h2] - mnew);
                mrun[mt][h2]  = mnew;
                float ps = 0.0f;
                #pragma unroll
                for (int nf = 0; nf < 8; nf++) {
                    float p0 = __expf(s[mt][nf][h2 * 2 + 0] - mnew);
                    float p1 = __expf(s[mt][nf][h2 * 2 + 1] - mnew);
                    s[mt][nf][h2 * 2 + 0] = p0;
                    s[mt][nf][h2 * 2 + 1] = p1;
                    ps += p0 + p1;
                }
                psum[mt][h2] = ps;
            }
        }
        #pragma unroll
        for (int mt = 0; mt < 2; mt++)
            #pragma unroll
            for (int nf = 0; nf < 8; nf++)
                #pragma unroll
                for (int e = 0; e < 4; e++)
                    o[mt][nf][e] *= alpha[mt][e >> 1];
        #pragma unroll
        for (int mt = 0; mt < 2; mt++)
            #pragma unroll
            for (int h2 = 0; h2 < 2; h2++) {
                psum[mt][h2] += __shfl_xor_sync(0xffffffffu, psum[mt][h2], 1);
                psum[mt][h2] += __shfl_xor_sync(0xffffffffu, psum[mt][h2], 2);
            }
        if (t == 0) {
            #pragma unroll
            for (int mt = 0; mt < 2; mt++)
                #pragma unroll
                for (int h2 = 0; h2 < 2; h2++)
                    redsum[wn * 128 + wm + mt * 16 + g + h2 * 8] = psum[mt][h2];
        }
        __syncthreads();
        #pragma unroll
        for (int mt = 0; mt < 2; mt++)
            #pragma unroll
            for (int h2 = 0; h2 < 2; h2++) {
                const int rl = wm + mt * 16 + g + h2 * 8;
                lrun[mt][h2] = lrun[mt][h2] * alpha[mt][h2] + redsum[rl] + redsum[128 + rl];
            }

        #pragma unroll
        for (int ks2 = 0; ks2 < 4; ks2++) {
            uint32_t ah[2][4];
            #pragma unroll
            for (int mt = 0; mt < 2; mt++) {
                ah[mt][0] = pack_h2(s[mt][2 * ks2][0],     s[mt][2 * ks2][1]);
                ah[mt][1] = pack_h2(s[mt][2 * ks2][2],     s[mt][2 * ks2][3]);
                ah[mt][2] = pack_h2(s[mt][2 * ks2 + 1][0], s[mt][2 * ks2 + 1][1]);
                ah[mt][3] = pack_h2(s[mt][2 * ks2 + 1][2], s[mt][2 * ks2 + 1][3]);
            }
            const int vcol = wn * 32 + ks2 * 8 + t;
            #pragma unroll
            for (int nf = 0; nf < 8; nf++) {
                const int rv = nf * 8 + g;
                const uint32_t b0 = Vh[rv][vcol], b1 = Vh[rv][vcol + 4];
                #pragma unroll
                for (int mt = 0; mt < 2; mt++)
                    mma_fp16(o[mt][nf], ah[mt][0], ah[mt][1], ah[mt][2], ah[mt][3], b0, b1);
            }
        }
    }

    __syncthreads();
    if (wn == 1) {
        #pragma unroll
        for (int mt = 0; mt < 2; mt++)
            #pragma unroll
            for (int h2 = 0; h2 < 2; h2++) {
                const int rl = wm + mt * 16 + g + h2 * 8;
                #pragma unroll
                for (int nf = 0; nf < 8; nf++) {
                    float2 v;
                    v.x = o[mt][nf][h2 * 2 + 0];
                    v.y = o[mt][nf][h2 * 2 + 1];
                    *(float2*)&Osum[rl * 66 + nf * 8 + 2 * t] = v;
                }
            }
    }
    __syncthreads();
    if (wn == 0) {
        #pragma unroll
        for (int mt = 0; mt < 2; mt++)
            #pragma unroll
            for (int h2 = 0; h2 < 2; h2++) {
                const int rl = wm + mt * 16 + g + h2 * 8;
                const float inv = 1.0f / lrun[mt][h2];
                #pragma unroll
                for (int nf = 0; nf < 8; nf++) {
                    const int c = nf * 8 + 2 * t;
                    float2 p = *(float2*)&Osum[rl * 66 + c];
                    const float vx = (o[mt][nf][h2 * 2 + 0] + p.x) * inv;
                    const float vy = (o[mt][nf][h2 * 2 + 1] + p.y) * inv;
                    g_Xh[(size_t)(b * 1024 + m0 + rl) * 512 + ((h * 64 + c) >> 1)] = pack_h2(vx, vy);
                }
            }
    }
}

// ---------------------------------------------------------------------------
// Kernel 4: out = gate * (X @ Winfo^T + binfo)  (gate read as fp16)
// ---------------------------------------------------------------------------
__global__ __launch_bounds__(256, 2) void info_kernel(
    const float* __restrict__ binfo, float* __restrict__ out)
{
    extern __shared__ uint32_t sm[];
    const int m0 = blockIdx.y * 128;
    const int n0 = blockIdx.x * 128;
    float acc[2][8][4] = {};
    gemm_fp16_ca(sm, g_Xh, 512, nullptr, 1 << 30, g_Wh + OW_INFO, 512, 512, m0, n0, acc);

    const int lane = threadIdx.x & 31, warp = threadIdx.x >> 5;
    const int wm = (warp & 3) * 32, wn = (warp >> 2) * 64;
    const int g = lane >> 2, t = lane & 3;

    #pragma unroll
    for (int nf = 0; nf < 8; nf++) {
        const int n = n0 + wn + nf * 8 + 2 * t;
        const float bx = binfo[n], by = binfo[n + 1];
        #pragma unroll
        for (int mt = 0; mt < 2; mt++) {
            #pragma unroll
            for (int h2 = 0; h2 < 2; h2++) {
                const int m = m0 + wm + mt * 16 + g + h2 * 8;
                const uint32_t gw = g_Gh[(size_t)m * 512 + (n >> 1)];
                const float2 gg = __half22float2(*(const __half2*)&gw);
                float2 v;
                v.x = gg.x * (acc[mt][nf][h2 * 2 + 0] + bx);
                v.y = gg.y * (acc[mt][nf][h2 * 2 + 1] + by);
                *(float2*)&out[(size_t)m * 1024 + n] = v;
            }
        }
    }
}

// ---------------------------------------------------------------------------
extern "C" void kernel_launch(void* const* d_in, const int* in_sizes, int n_in,
                              void* d_out, int out_size)
{
    (void)in_sizes; (void)n_in; (void)out_size;
    const float* query_g = (const float*)d_in[0];
    const float* key_g   = (const float*)d_in[1];
    const float* query_a = (const float*)d_in[2];
    const float* key_a   = (const float*)d_in[3];
    const float* value_a = (const float*)d_in[4];
    const int*   mask    = (const int*)  d_in[5];
    const float* Wqg = (const float*)d_in[6];  const float* bqg = (const float*)d_in[7];
    const float* Wkg = (const float*)d_in[8];  const float* bkg = (const float*)d_in[9];
    const float* Wqa = (const float*)d_in[10]; const float* bqa = (const float*)d_in[11];
    const float* Wka = (const float*)d_in[12]; const float* bka = (const float*)d_in[13];
    const float* Wva = (const float*)d_in[14]; const float* bva = (const float*)d_in[15];
    const float* Wgate = (const float*)d_in[16]; const float* bgate = (const float*)d_in[17];
    const float* Winfo = (const float*)d_in[18]; const float* binfo = (const float*)d_in[19];

    static int attr_set = 0;
    if (!attr_set) {
        cudaFuncSetAttribute(attn_kernel, cudaFuncAttributeMaxDynamicSharedMemorySize, ATTN_SMEM);
        cudaFuncSetAttribute(projgate_kernel, cudaFuncAttributeMaxDynamicSharedMemorySize, GSMEM);
        cudaFuncSetAttribute(info_kernel, cudaFuncAttributeMaxDynamicSharedMemorySize, GSMEM);
        attr_set = 1;
    }

    dim3 blk(256);
    conv_all_kernel<<<dim3(4096, 13), blk>>>(query_g, key_g, query_a, key_a, value_a,
                                             Wqa, Wqg, Wka, Wkg, Wva, Wgate, Winfo, mask);
    projgate_kernel<<<dim3(8, 32, 6), blk, GSMEM>>>(bqa, bqg, bka, bkg, bva, bgate);
    attn_kernel<<<dim3(8, 64), blk, ATTN_SMEM>>>();
    info_kernel<<<dim3(8, 32, 1), blk, GSMEM>>>(binfo, (float*)d_out);
}